// round 2
// baseline (speedup 1.0000x reference)
#include <cuda_runtime.h>

// Problem dims (fixed by reference)
static constexpr int BATCH = 4;
static constexpr int SEQ   = 2048;
static constexpr int DIM   = 1024;

// Scratch for Q, K, V projections (device globals: allocation-guard safe)
__device__ float g_q[BATCH * SEQ * DIM];
__device__ float g_k[BATCH * SEQ * DIM];
__device__ float g_v[BATCH * SEQ * DIM];

// ---------------------------------------------------------------------------
// Generic tiled fp32 GEMM.
//   C = alpha * A @ op(B) (+ bias)
//   A: [M,K] row-major.
//   BT=true : B stored [N,K] (i.e. compute A @ B^T)   -- QKV proj, Q@K^T
//   BT=false: B stored [K,N]                          -- AW @ V
// Batched via blockIdx.z with element strides sA/sB/sC.
// Tile: 64x64 output, K-step 16, 256 threads, 4x4 microtile per thread.
// All problem dims here are multiples of 64/16 -> no edge handling.
// ---------------------------------------------------------------------------
template <bool BT>
__global__ __launch_bounds__(256)
void gemm_kernel(const float* __restrict__ A,
                 const float* __restrict__ Bm,
                 const float* __restrict__ bias,
                 float* __restrict__ C,
                 int M, int N, int K, float alpha,
                 long sA, long sB, long sC)
{
    __shared__ float As[16][68];   // [k][m], 68 -> rows 16B-aligned for float4
    __shared__ float Bs[16][64];   // [k][n]

    const float* Ab = A  + (long)blockIdx.z * sA;
    const float* Bb = Bm + (long)blockIdx.z * sB;
    float*       Cb = C  + (long)blockIdx.z * sC;

    const int m0  = blockIdx.y * 64;
    const int n0  = blockIdx.x * 64;
    const int tid = threadIdx.x;
    const int tx  = tid & 15;        // microtile col group
    const int ty  = tid >> 4;        // microtile row group

    const int lrow = tid >> 2;        // 0..63  (A / B^T tile row)
    const int lcol = (tid & 3) << 2;  // 0,4,8,12 (k offset)
    const int brow = tid >> 4;        // 0..15  (B [K,N] tile row)
    const int bcol = (tid & 15) << 2; // 0..60

    float acc[4][4] = {};

    for (int k0 = 0; k0 < K; k0 += 16) {
        // Load A tile 64x16 (coalesced float4), store transposed As[k][m]
        float4 a4 = *(const float4*)(Ab + (long)(m0 + lrow) * K + k0 + lcol);
        As[lcol + 0][lrow] = a4.x;
        As[lcol + 1][lrow] = a4.y;
        As[lcol + 2][lrow] = a4.z;
        As[lcol + 3][lrow] = a4.w;

        if (BT) {
            // B [N,K]: same pattern as A
            float4 b4 = *(const float4*)(Bb + (long)(n0 + lrow) * K + k0 + lcol);
            Bs[lcol + 0][lrow] = b4.x;
            Bs[lcol + 1][lrow] = b4.y;
            Bs[lcol + 2][lrow] = b4.z;
            Bs[lcol + 3][lrow] = b4.w;
        } else {
            // B [K,N]: 16x64 tile, direct copy
            float4 b4 = *(const float4*)(Bb + (long)(k0 + brow) * N + n0 + bcol);
            *(float4*)&Bs[brow][bcol] = b4;
        }
        __syncthreads();

        #pragma unroll
        for (int k = 0; k < 16; ++k) {
            float4 av = *(const float4*)&As[k][ty << 2];
            float4 bv = *(const float4*)&Bs[k][tx << 2];
            float ar[4] = {av.x, av.y, av.z, av.w};
            float br[4] = {bv.x, bv.y, bv.z, bv.w};
            #pragma unroll
            for (int i = 0; i < 4; ++i)
                #pragma unroll
                for (int j = 0; j < 4; ++j)
                    acc[i][j] = fmaf(ar[i], br[j], acc[i][j]);
        }
        __syncthreads();
    }

    #pragma unroll
    for (int i = 0; i < 4; ++i) {
        const int m = m0 + (ty << 2) + i;
        #pragma unroll
        for (int j = 0; j < 4; ++j) {
            const int n = n0 + (tx << 2) + j;
            float v = acc[i][j] * alpha;
            if (bias) v += bias[n];
            Cb[(long)m * N + n] = v;
        }
    }
}

// ---------------------------------------------------------------------------
// In-place row softmax. One 256-thread block per row of 2048 elements.
// Values held in registers: one global load + one global store per element.
// ---------------------------------------------------------------------------
__global__ __launch_bounds__(256)
void softmax_kernel(float* __restrict__ data)
{
    constexpr int NC = SEQ;        // 2048
    constexpr int PT = NC / 256;   // 8 per thread

    float* row = data + (long)blockIdx.x * NC;
    __shared__ float red[8];

    const int tid  = threadIdx.x;
    const int lane = tid & 31;
    const int warp = tid >> 5;

    float v[PT];
    #pragma unroll
    for (int i = 0; i < PT; ++i) v[i] = row[tid + i * 256];

    // --- max reduce ---
    float lmax = v[0];
    #pragma unroll
    for (int i = 1; i < PT; ++i) lmax = fmaxf(lmax, v[i]);
    #pragma unroll
    for (int o = 16; o > 0; o >>= 1)
        lmax = fmaxf(lmax, __shfl_xor_sync(0xFFFFFFFFu, lmax, o));
    if (lane == 0) red[warp] = lmax;
    __syncthreads();
    float rmax = red[0];
    #pragma unroll
    for (int w = 1; w < 8; ++w) rmax = fmaxf(rmax, red[w]);
    __syncthreads();

    // --- exp + sum reduce ---
    float lsum = 0.0f;
    #pragma unroll
    for (int i = 0; i < PT; ++i) {
        v[i] = __expf(v[i] - rmax);
        lsum += v[i];
    }
    #pragma unroll
    for (int o = 16; o > 0; o >>= 1)
        lsum += __shfl_xor_sync(0xFFFFFFFFu, lsum, o);
    if (lane == 0) red[warp] = lsum;
    __syncthreads();
    float rsum = 0.0f;
    #pragma unroll
    for (int w = 0; w < 8; ++w) rsum += red[w];

    const float inv = 1.0f / rsum;
    #pragma unroll
    for (int i = 0; i < PT; ++i) row[tid + i * 256] = v[i] * inv;
}

// ---------------------------------------------------------------------------
// Launch: QKV proj -> scores -> softmax -> AV
// Output layout (tuple order): [weighted_sum B*S*D | attention_weights B*S*S]
// ---------------------------------------------------------------------------
extern "C" void kernel_launch(void* const* d_in, const int* in_sizes, int n_in,
                              void* d_out, int out_size)
{
    const float* x  = (const float*)d_in[0];
    const float* Wq = (const float*)d_in[1];
    const float* bq = (const float*)d_in[2];
    const float* Wk = (const float*)d_in[3];
    const float* bk = (const float*)d_in[4];
    const float* Wv = (const float*)d_in[5];
    const float* bv = (const float*)d_in[6];

    float* out_ws = (float*)d_out;                                  // [B,S,D]
    float* out_aw = (float*)d_out + (long)BATCH * SEQ * DIM;        // [B,S,S]

    float *q, *k, *v;
    cudaGetSymbolAddress((void**)&q, g_q);
    cudaGetSymbolAddress((void**)&k, g_k);
    cudaGetSymbolAddress((void**)&v, g_v);

    const dim3 blk(256);

    // 1) QKV projections: M = B*S = 8192, N = K = 1024, A@B^T + bias
    {
        dim3 grid(DIM / 64, (BATCH * SEQ) / 64, 1);
        gemm_kernel<true><<<grid, blk>>>(x, Wq, bq, q, BATCH * SEQ, DIM, DIM,
                                         1.0f, 0, 0, 0);
        gemm_kernel<true><<<grid, blk>>>(x, Wk, bk, k, BATCH * SEQ, DIM, DIM,
                                         1.0f, 0, 0, 0);
        gemm_kernel<true><<<grid, blk>>>(x, Wv, bv, v, BATCH * SEQ, DIM, DIM,
                                         1.0f, 0, 0, 0);
    }

    // 2) scores = (Q @ K^T) / sqrt(D), batched, written into attn-weight region
    {
        dim3 grid(SEQ / 64, SEQ / 64, BATCH);
        gemm_kernel<true><<<grid, blk>>>(q, k, nullptr, out_aw, SEQ, SEQ, DIM,
                                         0.03125f,
                                         (long)SEQ * DIM, (long)SEQ * DIM,
                                         (long)SEQ * SEQ);
    }

    // 3) row softmax in place on attention weights
    softmax_kernel<<<BATCH * SEQ, blk>>>(out_aw);

    // 4) weighted_sum = AW @ V  (B stored [K=S, N=D], non-transposed)
    {
        dim3 grid(DIM / 64, SEQ / 64, BATCH);
        gemm_kernel<false><<<grid, blk>>>(out_aw, v, nullptr, out_ws, SEQ, DIM,
                                          SEQ, 1.0f,
                                          (long)SEQ * SEQ, (long)SEQ * DIM,
                                          (long)SEQ * DIM);
    }
}

// round 3
// speedup vs baseline: 3.7008x; 3.7008x over previous
#include <cuda_runtime.h>
#include <cstdint>

static constexpr int BATCH = 4;
static constexpr int SEQ   = 2048;
static constexpr int DIM   = 1024;

// Scratch (device globals: allocation-guard safe)
__device__ float g_q[BATCH * SEQ * DIM];
__device__ float g_k[BATCH * SEQ * DIM];
__device__ float g_v[BATCH * SEQ * DIM];

// ---------------------------------------------------------------------------
// TF32 tensor-core GEMM:  C = alpha * A @ op(B) (+ bias)
//   A: [M,K] row-major.
//   BT=true : B stored [N,K]  (A @ B^T)   -- QKV proj, Q@K^T
//   BT=false: B stored [K,N]              -- AW @ V
// 128x128 block tile, BK=32, 256 threads (8 warps, 64x32 warp tiles),
// cp.async double-buffered SMEM, mma.sync.m16n8k8.tf32.
// All dims are multiples of 128/32 here -> no edge handling.
// ---------------------------------------------------------------------------

__device__ __forceinline__ uint32_t cvt_tf32(float x) {
    uint32_t u;
    asm volatile("cvt.rna.tf32.f32 %0, %1;" : "=r"(u) : "f"(x));
    return u;
}

__device__ __forceinline__ void mma_tf32(float (&c)[4],
                                         uint32_t a0, uint32_t a1,
                                         uint32_t a2, uint32_t a3,
                                         uint32_t b0, uint32_t b1) {
    asm volatile(
        "mma.sync.aligned.m16n8k8.row.col.f32.tf32.tf32.f32 "
        "{%0,%1,%2,%3}, {%4,%5,%6,%7}, {%8,%9}, {%0,%1,%2,%3};\n"
        : "+f"(c[0]), "+f"(c[1]), "+f"(c[2]), "+f"(c[3])
        : "r"(a0), "r"(a1), "r"(a2), "r"(a3), "r"(b0), "r"(b1));
}

#define CPA16(dst, src) \
    asm volatile("cp.async.cg.shared.global [%0], [%1], 16;\n" :: "r"(dst), "l"(src))

template <bool BT>
__global__ __launch_bounds__(256, 2)
void gemm_tc(const float* __restrict__ A, const float* __restrict__ B,
             const float* __restrict__ bias, float* __restrict__ C,
             int M, int N, int K, float alpha, long sA, long sB, long sC)
{
    constexpr int BM = 128, BN = 128, BK = 32;
    constexpr int APITCH = 36;                  // As row pitch (floats), 144B
    constexpr int BPITCH = BT ? 36 : 132;       // Bs row pitch
    constexpr int BROWS  = BT ? 128 : 32;
    constexpr int BS_OFF = 2 * BM * APITCH;     // float offset of Bs in smem

    extern __shared__ float smem[];
    float* As = smem;                           // [2][BM][APITCH]
    float* Bs = smem + BS_OFF;                  // [2][BROWS][BPITCH]
    const uint32_t sbase = (uint32_t)__cvta_generic_to_shared(smem);

    const float* Ab = A + (long)blockIdx.z * sA;
    const float* Bb = B + (long)blockIdx.z * sB;
    float*       Cb = C + (long)blockIdx.z * sC;

    const int n0   = blockIdx.x * BN;
    const int m0   = blockIdx.y * BM;
    const int tid  = threadIdx.x;
    const int warp = tid >> 5;
    const int lane = tid & 31;
    const int g    = lane >> 2;      // groupID (fragment row)
    const int tg   = lane & 3;       // thread-in-group (fragment col)
    const int wm   = (warp & 1) * 64;
    const int wn   = (warp >> 1) * 32;

    // global->smem load indices
    const int arow = tid >> 3;            // 0..31 (A / B^T rows)
    const int acol = (tid & 7) * 4;       // 0..28 (float4 column)
    const int brow = tid >> 5;            // 0..7  (B [K,N] rows)
    const int bcol = (tid & 31) * 4;      // 0..124

    float acc[4][4][4];
    #pragma unroll
    for (int i = 0; i < 4; ++i)
        #pragma unroll
        for (int j = 0; j < 4; ++j)
            #pragma unroll
            for (int r = 0; r < 4; ++r) acc[i][j][r] = 0.0f;

    auto load_tile = [&](int kt, int buf) {
        const int k0 = kt * BK;
        #pragma unroll
        for (int i = 0; i < 4; ++i) {
            int r = arow + i * 32;
            uint32_t dst = sbase + (uint32_t)(((buf * BM + r) * APITCH + acol) * 4);
            CPA16(dst, Ab + (long)(m0 + r) * K + k0 + acol);
        }
        if (BT) {
            #pragma unroll
            for (int i = 0; i < 4; ++i) {
                int r = arow + i * 32;
                uint32_t dst = sbase + (uint32_t)((BS_OFF + (buf * BROWS + r) * BPITCH + acol) * 4);
                CPA16(dst, Bb + (long)(n0 + r) * K + k0 + acol);
            }
        } else {
            #pragma unroll
            for (int i = 0; i < 4; ++i) {
                int r = brow + i * 8;
                uint32_t dst = sbase + (uint32_t)((BS_OFF + (buf * BROWS + r) * BPITCH + bcol) * 4);
                CPA16(dst, Bb + (long)(k0 + r) * N + n0 + bcol);
            }
        }
        asm volatile("cp.async.commit_group;\n");
    };

    const int ntiles = K / BK;
    load_tile(0, 0);

    for (int kt = 0; kt < ntiles; ++kt) {
        const int buf = kt & 1;
        if (kt + 1 < ntiles) {
            load_tile(kt + 1, buf ^ 1);
            asm volatile("cp.async.wait_group 1;\n");
        } else {
            asm volatile("cp.async.wait_group 0;\n");
        }
        __syncthreads();

        #pragma unroll
        for (int kk = 0; kk < 4; ++kk) {
            const int k = kk * 8;
            uint32_t af[4][4];
            #pragma unroll
            for (int mi = 0; mi < 4; ++mi) {
                const float* ap = &As[(buf * BM + wm + mi * 16 + g) * APITCH + k];
                af[mi][0] = cvt_tf32(ap[tg]);
                af[mi][1] = cvt_tf32(ap[8 * APITCH + tg]);
                af[mi][2] = cvt_tf32(ap[tg + 4]);
                af[mi][3] = cvt_tf32(ap[8 * APITCH + tg + 4]);
            }
            uint32_t bf[4][2];
            #pragma unroll
            for (int ni = 0; ni < 4; ++ni) {
                if (BT) {
                    const float* bp = &Bs[(buf * BROWS + wn + ni * 8 + g) * BPITCH + k];
                    bf[ni][0] = cvt_tf32(bp[tg]);
                    bf[ni][1] = cvt_tf32(bp[tg + 4]);
                } else {
                    const float* bp = &Bs[(buf * BROWS + k + tg) * BPITCH + wn + ni * 8 + g];
                    bf[ni][0] = cvt_tf32(bp[0]);
                    bf[ni][1] = cvt_tf32(bp[4 * BPITCH]);
                }
            }
            #pragma unroll
            for (int mi = 0; mi < 4; ++mi)
                #pragma unroll
                for (int ni = 0; ni < 4; ++ni)
                    mma_tf32(acc[mi][ni], af[mi][0], af[mi][1], af[mi][2], af[mi][3],
                             bf[ni][0], bf[ni][1]);
        }
        __syncthreads();
    }

    // Epilogue
    #pragma unroll
    for (int mi = 0; mi < 4; ++mi) {
        const int row = m0 + wm + mi * 16 + g;
        #pragma unroll
        for (int ni = 0; ni < 4; ++ni) {
            const int col = n0 + wn + ni * 8 + tg * 2;
            float2 v0 = make_float2(acc[mi][ni][0] * alpha, acc[mi][ni][1] * alpha);
            float2 v1 = make_float2(acc[mi][ni][2] * alpha, acc[mi][ni][3] * alpha);
            if (bias) {
                float2 b = *(const float2*)&bias[col];
                v0.x += b.x; v0.y += b.y; v1.x += b.x; v1.y += b.y;
            }
            *(float2*)&Cb[(long)row * N + col]       = v0;
            *(float2*)&Cb[(long)(row + 8) * N + col] = v1;
        }
    }
}

// ---------------------------------------------------------------------------
// In-place row softmax: one 256-thread block per 2048-element row.
// ---------------------------------------------------------------------------
__global__ __launch_bounds__(256)
void softmax_kernel(float* __restrict__ data)
{
    constexpr int NC = SEQ;
    constexpr int PT = NC / 256;

    float* row = data + (long)blockIdx.x * NC;
    __shared__ float red[8];

    const int tid  = threadIdx.x;
    const int lane = tid & 31;
    const int warp = tid >> 5;

    float v[PT];
    #pragma unroll
    for (int i = 0; i < PT; ++i) v[i] = row[tid + i * 256];

    float lmax = v[0];
    #pragma unroll
    for (int i = 1; i < PT; ++i) lmax = fmaxf(lmax, v[i]);
    #pragma unroll
    for (int o = 16; o > 0; o >>= 1)
        lmax = fmaxf(lmax, __shfl_xor_sync(0xFFFFFFFFu, lmax, o));
    if (lane == 0) red[warp] = lmax;
    __syncthreads();
    float rmax = red[0];
    #pragma unroll
    for (int w = 1; w < 8; ++w) rmax = fmaxf(rmax, red[w]);
    __syncthreads();

    float lsum = 0.0f;
    #pragma unroll
    for (int i = 0; i < PT; ++i) {
        v[i] = __expf(v[i] - rmax);
        lsum += v[i];
    }
    #pragma unroll
    for (int o = 16; o > 0; o >>= 1)
        lsum += __shfl_xor_sync(0xFFFFFFFFu, lsum, o);
    if (lane == 0) red[warp] = lsum;
    __syncthreads();
    float rsum = 0.0f;
    #pragma unroll
    for (int w = 0; w < 8; ++w) rsum += red[w];

    const float inv = 1.0f / rsum;
    #pragma unroll
    for (int i = 0; i < PT; ++i) row[tid + i * 256] = v[i] * inv;
}

// ---------------------------------------------------------------------------
// Launch: QKV proj -> scores -> softmax -> AV
// Output layout: [weighted_sum B*S*D | attention_weights B*S*S]
// ---------------------------------------------------------------------------
extern "C" void kernel_launch(void* const* d_in, const int* in_sizes, int n_in,
                              void* d_out, int out_size)
{
    const float* x  = (const float*)d_in[0];
    const float* Wq = (const float*)d_in[1];
    const float* bq = (const float*)d_in[2];
    const float* Wk = (const float*)d_in[3];
    const float* bk = (const float*)d_in[4];
    const float* Wv = (const float*)d_in[5];
    const float* bv = (const float*)d_in[6];

    float* out_ws = (float*)d_out;
    float* out_aw = (float*)d_out + (long)BATCH * SEQ * DIM;

    float *q, *k, *v;
    cudaGetSymbolAddress((void**)&q, g_q);
    cudaGetSymbolAddress((void**)&k, g_k);
    cudaGetSymbolAddress((void**)&v, g_v);

    // Dynamic SMEM sizes: BT = 73728 B, non-BT = 70656 B
    const int smem_bt  = 73728;
    const int smem_nbt = 70656;
    cudaFuncSetAttribute(gemm_tc<true>,  cudaFuncAttributeMaxDynamicSharedMemorySize, smem_bt);
    cudaFuncSetAttribute(gemm_tc<false>, cudaFuncAttributeMaxDynamicSharedMemorySize, smem_nbt);

    const dim3 blk(256);

    // 1) QKV projections: [8192,1024] = x[8192,1024] @ W^T + b
    {
        dim3 grid(DIM / 128, (BATCH * SEQ) / 128, 1);
        gemm_tc<true><<<grid, blk, smem_bt>>>(x, Wq, bq, q, BATCH * SEQ, DIM, DIM,
                                              1.0f, 0, 0, 0);
        gemm_tc<true><<<grid, blk, smem_bt>>>(x, Wk, bk, k, BATCH * SEQ, DIM, DIM,
                                              1.0f, 0, 0, 0);
        gemm_tc<true><<<grid, blk, smem_bt>>>(x, Wv, bv, v, BATCH * SEQ, DIM, DIM,
                                              1.0f, 0, 0, 0);
    }

    // 2) scores = (Q @ K^T) / 32, batched over B, into attention-weights region
    {
        dim3 grid(SEQ / 128, SEQ / 128, BATCH);
        gemm_tc<true><<<grid, blk, smem_bt>>>(q, k, nullptr, out_aw, SEQ, SEQ, DIM,
                                              0.03125f,
                                              (long)SEQ * DIM, (long)SEQ * DIM,
                                              (long)SEQ * SEQ);
    }

    // 3) softmax rows in place
    softmax_kernel<<<BATCH * SEQ, blk>>>(out_aw);

    // 4) weighted_sum = AW @ V   (B stored [K=S, N=D])
    {
        dim3 grid(DIM / 128, SEQ / 128, BATCH);
        gemm_tc<false><<<grid, blk, smem_nbt>>>(out_aw, v, nullptr, out_ws, SEQ, DIM,
                                                SEQ, 1.0f,
                                                (long)SEQ * SEQ, (long)SEQ * DIM,
                                                (long)SEQ * DIM);
    }
}

// round 5
// speedup vs baseline: 3.8922x; 1.0517x over previous
#include <cuda_runtime.h>
#include <cstdint>

static constexpr int BATCH = 4;
static constexpr int SEQ   = 2048;
static constexpr int DIM   = 1024;

// Scratch (device globals: allocation-guard safe)
__device__ float g_x [BATCH * SEQ * DIM];   // tf32-rounded x
__device__ float g_wq[DIM * DIM];           // tf32-rounded weights
__device__ float g_wk[DIM * DIM];
__device__ float g_wv[DIM * DIM];
__device__ float g_q [BATCH * SEQ * DIM];   // tf32-rounded Q
__device__ float g_k [BATCH * SEQ * DIM];   // tf32-rounded K
__device__ float g_v [BATCH * SEQ * DIM];   // tf32-rounded V
__device__ float g_p [BATCH * SEQ * SEQ];   // tf32-rounded attention weights

// ---------------------------------------------------------------------------
__device__ __forceinline__ uint32_t smem_u32(const void* p) {
    uint32_t a;
    asm("{ .reg .u64 t; cvta.to.shared.u64 t, %1; cvt.u32.u64 %0, t; }"
        : "=r"(a) : "l"(p));
    return a;
}

__device__ __forceinline__ float round_tf32(float x) {
    uint32_t u;
    asm("cvt.rna.tf32.f32 %0, %1;" : "=r"(u) : "f"(x));
    return __uint_as_float(u);
}

__device__ __forceinline__ void mma_tf32(float (&c)[4],
                                         uint32_t a0, uint32_t a1,
                                         uint32_t a2, uint32_t a3,
                                         uint32_t b0, uint32_t b1) {
    asm volatile(
        "mma.sync.aligned.m16n8k8.row.col.f32.tf32.tf32.f32 "
        "{%0,%1,%2,%3}, {%4,%5,%6,%7}, {%8,%9}, {%0,%1,%2,%3};\n"
        : "+f"(c[0]), "+f"(c[1]), "+f"(c[2]), "+f"(c[3])
        : "r"(a0), "r"(a1), "r"(a2), "r"(a3), "r"(b0), "r"(b1));
}

#define CPA16(dst, src) \
    asm volatile("cp.async.cg.shared.global [%0], [%1], 16;\n" :: "r"(dst), "l"(src))

// ---------------------------------------------------------------------------
// Elementwise tf32 rounding pass (float4 grid-stride)
// ---------------------------------------------------------------------------
__global__ __launch_bounds__(256)
void round_kernel(const float* __restrict__ in, float* __restrict__ out, int n4)
{
    int i = blockIdx.x * 256 + threadIdx.x;
    if (i < n4) {
        float4 v = ((const float4*)in)[i];
        v.x = round_tf32(v.x);
        v.y = round_tf32(v.y);
        v.z = round_tf32(v.z);
        v.w = round_tf32(v.w);
        ((float4*)out)[i] = v;
    }
}

// ---------------------------------------------------------------------------
// TF32 tensor-core GEMM, cvt-free inner loop (operands pre-rounded).
//   C = alpha * A @ op(B) (+ bias)  [optionally tf32-rounded on store]
//   A: [M,K] row-major.
//   BT=true : B stored [N,K]  (A @ B^T)
//   BT=false: B stored [K,N]
// Block tile 128x256, BK=32, 3-stage cp.async, 8 warps, warp tile 64x64.
// All dims are multiples of the tile sizes (no edge handling).
// ---------------------------------------------------------------------------
template <bool BT, bool ROUND_OUT>
__global__ __launch_bounds__(256, 1)
void gemm_tc(const float* __restrict__ A, const float* __restrict__ B,
             const float* __restrict__ bias, float* __restrict__ C,
             int M, int N, int K, float alpha, long sA, long sB, long sC)
{
    constexpr int BM = 128, BN = 256, BK = 32, NST = 3;
    constexpr int AP = 36;                 // As pitch (floats): bank 4g+tg, conflict-free
    constexpr int BP = BT ? 36 : 264;      // Bs pitch: BT 4g+tg / nBT 8tg+g, conflict-free
    constexpr int BR = BT ? BN : BK;       // Bs rows
    constexpr int ASZ = BM * AP;           // floats/stage
    constexpr int BSZ = BR * BP;
    constexpr int STG = ASZ + BSZ;

    extern __shared__ float sm[];
    const uint32_t sbase = smem_u32(sm);

    const float* Ab = A + (long)blockIdx.z * sA;
    const float* Bb = B + (long)blockIdx.z * sB;
    float*       Cb = C + (long)blockIdx.z * sC;
    const int m0 = blockIdx.y * BM;
    const int n0 = blockIdx.x * BN;

    const int tid  = threadIdx.x;
    const int warp = tid >> 5;
    const int lane = tid & 31;
    const int g    = lane >> 2;
    const int tg   = lane & 3;
    const int wm   = (warp & 1) * 64;      // 2 warps over M
    const int wn   = (warp >> 1) * 64;     // 4 warps over N

    float acc[4][8][4];
    #pragma unroll
    for (int i = 0; i < 4; ++i)
        #pragma unroll
        for (int j = 0; j < 8; ++j)
            #pragma unroll
            for (int r = 0; r < 4; ++r) acc[i][j][r] = 0.0f;

    auto load_tile = [&](int kt, int s) {
        const int k0 = kt * BK;
        const uint32_t a_off = sbase + (uint32_t)(s * STG) * 4u;
        const uint32_t b_off = a_off + (uint32_t)ASZ * 4u;
        #pragma unroll
        for (int i = 0; i < 4; ++i) {            // A: 128 rows x 8 chunks
            int ci = tid + i * 256;
            int r = ci >> 3, c = ci & 7;
            CPA16(a_off + (uint32_t)(r * AP + c * 4) * 4u,
                  Ab + (long)(m0 + r) * K + k0 + c * 4);
        }
        if (BT) {
            #pragma unroll
            for (int i = 0; i < 8; ++i) {        // B^T: 256 rows x 8 chunks
                int ci = tid + i * 256;
                int r = ci >> 3, c = ci & 7;
                CPA16(b_off + (uint32_t)(r * BP + c * 4) * 4u,
                      Bb + (long)(n0 + r) * K + k0 + c * 4);
            }
        } else {
            #pragma unroll
            for (int i = 0; i < 8; ++i) {        // B: 32 rows x 64 chunks
                int ci = tid + i * 256;
                int r = ci >> 6, c = ci & 63;
                CPA16(b_off + (uint32_t)(r * BP + c * 4) * 4u,
                      Bb + (long)(k0 + r) * N + n0 + c * 4);
            }
        }
        asm volatile("cp.async.commit_group;\n");
    };

    const int ntiles = K / BK;

    load_tile(0, 0);
    load_tile(1, 1);

    for (int kt = 0; kt < ntiles; ++kt) {
        const int s = kt % NST;
        if (kt + 2 < ntiles) load_tile(kt + 2, (kt + 2) % NST);
        else asm volatile("cp.async.commit_group;\n");
        asm volatile("cp.async.wait_group %0;\n" :: "n"(NST - 1));
        __syncthreads();

        const float* As = sm + s * STG;
        const float* Bs = As + ASZ;

        #pragma unroll
        for (int kk = 0; kk < 4; ++kk) {
            const int k = kk * 8;
            uint32_t af[4][4];
            #pragma unroll
            for (int mi = 0; mi < 4; ++mi) {
                const float* ap = &As[(wm + mi * 16 + g) * AP + k];
                af[mi][0] = __float_as_uint(ap[tg]);
                af[mi][1] = __float_as_uint(ap[8 * AP + tg]);
                af[mi][2] = __float_as_uint(ap[tg + 4]);
                af[mi][3] = __float_as_uint(ap[8 * AP + tg + 4]);
            }
            uint32_t bf[8][2];
            #pragma unroll
            for (int ni = 0; ni < 8; ++ni) {
                if (BT) {
                    const float* bp = &Bs[(wn + ni * 8 + g) * BP + k];
                    bf[ni][0] = __float_as_uint(bp[tg]);
                    bf[ni][1] = __float_as_uint(bp[tg + 4]);
                } else {
                    const float* bp = &Bs[(k + tg) * BP + wn + ni * 8 + g];
                    bf[ni][0] = __float_as_uint(bp[0]);
                    bf[ni][1] = __float_as_uint(bp[4 * BP]);
                }
            }
            #pragma unroll
            for (int mi = 0; mi < 4; ++mi)
                #pragma unroll
                for (int ni = 0; ni < 8; ++ni)
                    mma_tf32(acc[mi][ni], af[mi][0], af[mi][1], af[mi][2],
                             af[mi][3], bf[ni][0], bf[ni][1]);
        }
        __syncthreads();
    }

    // Epilogue
    #pragma unroll
    for (int mi = 0; mi < 4; ++mi) {
        const int row = m0 + wm + mi * 16 + g;
        #pragma unroll
        for (int ni = 0; ni < 8; ++ni) {
            const int col = n0 + wn + ni * 8 + tg * 2;
            float2 v0 = make_float2(acc[mi][ni][0] * alpha, acc[mi][ni][1] * alpha);
            float2 v1 = make_float2(acc[mi][ni][2] * alpha, acc[mi][ni][3] * alpha);
            if (bias) {
                float2 b = *(const float2*)&bias[col];
                v0.x += b.x; v0.y += b.y; v1.x += b.x; v1.y += b.y;
            }
            if (ROUND_OUT) {
                v0.x = round_tf32(v0.x); v0.y = round_tf32(v0.y);
                v1.x = round_tf32(v1.x); v1.y = round_tf32(v1.y);
            }
            *(float2*)&Cb[(long)row * N + col]       = v0;
            *(float2*)&Cb[(long)(row + 8) * N + col] = v1;
        }
    }
}

// ---------------------------------------------------------------------------
// In-place row softmax + tf32-rounded secondary output for the AV GEMM.
// ---------------------------------------------------------------------------
__global__ __launch_bounds__(256)
void softmax_kernel(float* __restrict__ data, float* __restrict__ rounded)
{
    constexpr int NC = SEQ;
    constexpr int PT = NC / 256;

    const long roff = (long)blockIdx.x * NC;
    float* row = data + roff;
    float* rr  = rounded + roff;
    __shared__ float red[8];

    const int tid  = threadIdx.x;
    const int lane = tid & 31;
    const int warp = tid >> 5;

    float v[PT];
    #pragma unroll
    for (int i = 0; i < PT; ++i) v[i] = row[tid + i * 256];

    float lmax = v[0];
    #pragma unroll
    for (int i = 1; i < PT; ++i) lmax = fmaxf(lmax, v[i]);
    #pragma unroll
    for (int o = 16; o > 0; o >>= 1)
        lmax = fmaxf(lmax, __shfl_xor_sync(0xFFFFFFFFu, lmax, o));
    if (lane == 0) red[warp] = lmax;
    __syncthreads();
    float rmax = red[0];
    #pragma unroll
    for (int w = 1; w < 8; ++w) rmax = fmaxf(rmax, red[w]);
    __syncthreads();

    float lsum = 0.0f;
    #pragma unroll
    for (int i = 0; i < PT; ++i) {
        v[i] = __expf(v[i] - rmax);
        lsum += v[i];
    }
    #pragma unroll
    for (int o = 16; o > 0; o >>= 1)
        lsum += __shfl_xor_sync(0xFFFFFFFFu, lsum, o);
    if (lane == 0) red[warp] = lsum;
    __syncthreads();
    float rsum = 0.0f;
    #pragma unroll
    for (int w = 0; w < 8; ++w) rsum += red[w];

    const float inv = 1.0f / rsum;
    #pragma unroll
    for (int i = 0; i < PT; ++i) {
        const float o = v[i] * inv;
        row[tid + i * 256] = o;
        rr [tid + i * 256] = round_tf32(o);
    }
}

// ---------------------------------------------------------------------------
// Launch: round(x,W) -> QKV proj -> scores -> softmax -> AV
// Output layout: [weighted_sum B*S*D | attention_weights B*S*S]
// ---------------------------------------------------------------------------
extern "C" void kernel_launch(void* const* d_in, const int* in_sizes, int n_in,
                              void* d_out, int out_size)
{
    const float* x  = (const float*)d_in[0];
    const float* Wq = (const float*)d_in[1];
    const float* bq = (const float*)d_in[2];
    const float* Wk = (const float*)d_in[3];
    const float* bk = (const float*)d_in[4];
    const float* Wv = (const float*)d_in[5];
    const float* bv = (const float*)d_in[6];

    float* out_ws = (float*)d_out;
    float* out_aw = (float*)d_out + (long)BATCH * SEQ * DIM;

    float *xr, *wq, *wk, *wv, *q, *k, *v, *p;
    cudaGetSymbolAddress((void**)&xr, g_x);
    cudaGetSymbolAddress((void**)&wq, g_wq);
    cudaGetSymbolAddress((void**)&wk, g_wk);
    cudaGetSymbolAddress((void**)&wv, g_wv);
    cudaGetSymbolAddress((void**)&q,  g_q);
    cudaGetSymbolAddress((void**)&k,  g_k);
    cudaGetSymbolAddress((void**)&v,  g_v);
    cudaGetSymbolAddress((void**)&p,  g_p);

    // SMEM sizes (floats/stage * 3 stages * 4B)
    const int smem_bt  = 3 * (128 * 36 + 256 * 36) * 4;   // 165888
    const int smem_nbt = 3 * (128 * 36 + 32 * 264) * 4;   // 156672
    cudaFuncSetAttribute(gemm_tc<true,  true >, cudaFuncAttributeMaxDynamicSharedMemorySize, smem_bt);
    cudaFuncSetAttribute(gemm_tc<true,  false>, cudaFuncAttributeMaxDynamicSharedMemorySize, smem_bt);
    cudaFuncSetAttribute(gemm_tc<false, false>, cudaFuncAttributeMaxDynamicSharedMemorySize, smem_nbt);

    const dim3 blk(256);

    // 0) pre-round inputs to tf32 grid
    {
        const int nx = BATCH * SEQ * DIM / 4;
        const int nw = DIM * DIM / 4;
        round_kernel<<<(nx + 255) / 256, blk>>>(x,  xr, nx);
        round_kernel<<<(nw + 255) / 256, blk>>>(Wq, wq, nw);
        round_kernel<<<(nw + 255) / 256, blk>>>(Wk, wk, nw);
        round_kernel<<<(nw + 255) / 256, blk>>>(Wv, wv, nw);
    }

    // 1) QKV projections: [8192,1024] = xr @ W^T + b, tf32-rounded outputs
    {
        dim3 grid(DIM / 256, (BATCH * SEQ) / 128, 1);
        gemm_tc<true, true><<<grid, blk, smem_bt>>>(xr, wq, bq, q,
                                                    BATCH * SEQ, DIM, DIM, 1.0f, 0, 0, 0);
        gemm_tc<true, true><<<grid, blk, smem_bt>>>(xr, wk, bk, k,
                                                    BATCH * SEQ, DIM, DIM, 1.0f, 0, 0, 0);
        gemm_tc<true, true><<<grid, blk, smem_bt>>>(xr, wv, bv, v,
                                                    BATCH * SEQ, DIM, DIM, 1.0f, 0, 0, 0);
    }

    // 2) scores = (Q @ K^T) / 32, batched, exact fp32 store
    {
        dim3 grid(SEQ / 256, SEQ / 128, BATCH);
        gemm_tc<true, false><<<grid, blk, smem_bt>>>(q, k, nullptr, out_aw,
                                                     SEQ, SEQ, DIM, 0.03125f,
                                                     (long)SEQ * DIM, (long)SEQ * DIM,
                                                     (long)SEQ * SEQ);
    }

    // 3) softmax: exact -> out_aw, tf32-rounded -> p
    softmax_kernel<<<BATCH * SEQ, blk>>>(out_aw, p);

    // 4) weighted_sum = P @ V   (B stored [K=S, N=D])
    {
        dim3 grid(DIM / 256, SEQ / 128, BATCH);
        gemm_tc<false, false><<<grid, blk, smem_nbt>>>(p, v, nullptr, out_ws,
                                                       SEQ, DIM, SEQ, 1.0f,
                                                       (long)SEQ * SEQ, (long)SEQ * DIM,
                                                       (long)SEQ * DIM);
    }
}